// round 3
// baseline (speedup 1.0000x reference)
#include <cuda_runtime.h>

// Problem constants
#define BB 32
#define CC 256
#define HH 32
#define WW 32
#define KK 1024
#define NN 1024                      // H*W
#define ZP_BATCH (CC * NN)           // 262144 floats per batch
#define ZQ_SIZE (BB * CC * HH * WW)  // 8388608
#define IDX_SIZE (BB * NN)           // 32768

// GEMM smem layout (floats):
//   [0, 32768)        Msm  [256][128] persistent M panel
//   [32768, 32896)    z2s  [128]
//   [32896, 49280)    EsB  [2][16c][256k][2dup] E double buffer (aliased by sval/sidx at end)
#define SMEM_FLOATS 49280
#define SMEM_BYTES (SMEM_FLOATS * 4)   // 197120 B

typedef unsigned long long ull;

// Device scratch (allocation-free rule: __device__ globals)
__device__ float g_zp[BB * ZP_BATCH];   // z permuted to [b][h][w][c] contiguous
__device__ float g_e2[KK];              // ||E_k||^2
__device__ int   g_idx[BB * NN];        // argmin indices
__device__ float g_losspart[1024];      // per-block loss partials (deterministic reduce)

// ---------- packed f32x2 helpers (sm_100+ PTX) ----------
__device__ __forceinline__ ull pack2(float lo, float hi) {
    ull r;
    asm("mov.b64 %0, {%1, %2};" : "=l"(r) : "f"(lo), "f"(hi));
    return r;
}
__device__ __forceinline__ void unpack2(ull v, float& lo, float& hi) {
    asm("mov.b64 {%0, %1}, %2;" : "=f"(lo), "=f"(hi) : "l"(v));
}
__device__ __forceinline__ void fma2(ull& d, ull a, ull b) {
    asm("fma.rn.f32x2 %0, %1, %2, %0;" : "+l"(d) : "l"(a), "l"(b));
}

// ---------- kernel 1: e2[k] = sum_c E[k][c]^2 (warp per k) ----------
__global__ void k_e2(const float* __restrict__ E) {
    int warp = threadIdx.x >> 5, lane = threadIdx.x & 31;
    int k = blockIdx.x * 8 + warp;   // 128 blocks * 8 warps = 1024
    const float* row = E + k * CC;
    float s = 0.f;
#pragma unroll
    for (int i = 0; i < 8; i++) { float v = row[lane + 32 * i]; s = fmaf(v, v, s); }
#pragma unroll
    for (int o = 16; o; o >>= 1) s += __shfl_xor_sync(0xFFFFFFFFu, s, o);
    if (lane == 0) g_e2[k] = s;
}

// ---------- kernel 2: transpose z[b,c,h,w] -> g_zp[b][h][w][c] ----------
__global__ void k_tr(const float* __restrict__ z) {
    __shared__ float s[CC][33];       // padded: conflict-free both phases
    int b = blockIdx.x >> 5, h = blockIdx.x & 31;
    int w = threadIdx.x & 31, t8 = threadIdx.x >> 5;  // t8 in [0,8)
    const float* zp = z + ((long long)(b * CC) * HH + h) * WW + w;
#pragma unroll
    for (int i = 0; i < 32; i++) {
        int c = t8 * 32 + i;
        s[c][w] = zp[(long long)c * HH * WW];
    }
    __syncthreads();
    float* out = g_zp + (long long)b * ZP_BATCH + h * (WW * CC);
#pragma unroll
    for (int i = 0; i < 32; i++) {
        int f = threadIdx.x + i * 256;     // 0..8191 contiguous output
        int c = f & 255, ww = f >> 8;
        out[f] = s[c][ww];
    }
}

// ---------- kernel 3: fused GEMM (f32x2) + argmin ----------
// dist[k][n] = (e2[k] + z2[n]) - 2 * sum_c E[k][c] * M[c][n]
// 512 threads = (ty 32) x (tx 16). Block tile: 1024 k x 128 n, 4 k-slabs of 256.
__global__ void __launch_bounds__(512) k_gemm(const float* __restrict__ E,
                                              float* __restrict__ dout, int out_size) {
    extern __shared__ float sm[];
    float* Msm = sm;                   // [256][128]
    float* z2s = sm + 32768;           // [128]
    float* EsB = sm + 32896;           // [2][16][256][2]
    float* sval = EsB;                 // [32][128]   (aliased after main loop)
    int*   sidx = (int*)(EsB + 4096);  // [32][128]

    int tid = threadIdx.x;
    int ty = tid >> 4, tx = tid & 15;  // ty in [0,32)
    int b = blockIdx.x >> 3;
    int n0 = (blockIdx.x & 7) * 128;
    const float* Mb = g_zp + (long long)b * ZP_BATCH;

    // ---- load persistent M panel [256][128], coalesced ----
    {
        int lane4 = (tid & 31) * 4, w16 = tid >> 5;   // warp id 0..15
#pragma unroll
        for (int i = 0; i < 16; i++) {
            int c = w16 + i * 16;
            *(float4*)&Msm[c * 128 + lane4] = *(const float4*)&Mb[c * NN + n0 + lane4];
        }
    }
    __syncthreads();

    // ---- E chunk staging roles: each thread loads 8 E floats per chunk ----
    int ek = tid >> 1, ec = (tid & 1) * 8;    // ek: k-local 0..255, ec: c-in-chunk {0,8}
    float4 pre0, pre1;
    {
        const float* ep = &E[ek * CC + ec];   // chunk 0 of slab 0
        pre0 = *(const float4*)ep;
        pre1 = *(const float4*)(ep + 4);
    }
    if (tid < 128) {
        float s = 0.f;
#pragma unroll 8
        for (int c = 0; c < CC; c++) { float v = Msm[c * 128 + tid]; s = fmaf(v, v, s); }
        z2s[tid] = s;
    }
    // store chunk 0 into buffer 0, duplicated pairs
    {
        float v[8] = {pre0.x, pre0.y, pre0.z, pre0.w, pre1.x, pre1.y, pre1.z, pre1.w};
#pragma unroll
        for (int j = 0; j < 8; j++)
            *(ull*)&EsB[(ec + j) * 512 + ek * 2] = pack2(v[j], v[j]);
    }
    __syncthreads();

    float z2v[8];
#pragma unroll
    for (int j = 0; j < 8; j++) z2v[j] = z2s[tx * 8 + j];

    float best_v[8];
    int   best_k[8];
#pragma unroll
    for (int j = 0; j < 8; j++) { best_v[j] = 3.4e38f; best_k[j] = 0; }

    int buf = 0;
    for (int ko = 0; ko < 4; ko++) {       // k-slab of 256
        ull acc[8][4];
#pragma unroll
        for (int i = 0; i < 8; i++)
#pragma unroll
            for (int j = 0; j < 4; j++) acc[i][j] = 0ull;

        for (int ch = 0; ch < 16; ch++) {  // c-chunk of 16
            int q = ko * 16 + ch;
            bool more = (q + 1 < 64);
            if (more) {
                int nk0 = ((q + 1) >> 4) * 256, nc0 = ((q + 1) & 15) * 16;
                const float* ep = &E[(nk0 + ek) * CC + nc0 + ec];
                pre0 = *(const float4*)ep;
                pre1 = *(const float4*)(ep + 4);
            }
            const float* Ec = EsB + buf * 8192;
#pragma unroll 2
            for (int cc = 0; cc < 16; cc++) {
                const ull* pb = (const ull*)&Msm[(ch * 16 + cc) * 128 + tx * 8];
                ull b0 = pb[0], b1 = pb[1], b2 = pb[2], b3 = pb[3];
                const ull* pa = (const ull*)&Ec[cc * 512 + ty * 16];
#pragma unroll
                for (int i = 0; i < 8; i++) {
                    ull ad = pa[i];
                    fma2(acc[i][0], ad, b0);
                    fma2(acc[i][1], ad, b1);
                    fma2(acc[i][2], ad, b2);
                    fma2(acc[i][3], ad, b3);
                }
            }
            if (more) {
                float* EsN = EsB + (buf ^ 1) * 8192;
                float v[8] = {pre0.x, pre0.y, pre0.z, pre0.w, pre1.x, pre1.y, pre1.z, pre1.w};
#pragma unroll
                for (int j = 0; j < 8; j++)
                    *(ull*)&EsN[(ec + j) * 512 + ek * 2] = pack2(v[j], v[j]);
            }
            __syncthreads();
            buf ^= 1;
        }

        // fold this k-slab into running argmin (first-min tie-break via k compare)
        int k0 = ko * 256;
#pragma unroll
        for (int i = 0; i < 8; i++) {
            int kg = k0 + ty * 8 + i;
            float e2k = g_e2[kg];
#pragma unroll
            for (int j2 = 0; j2 < 4; j2++) {
                float d0, d1;
                unpack2(acc[i][j2], d0, d1);
                {
                    int j = j2 * 2;
                    float dist = (e2k + z2v[j]) - 2.0f * d0;
                    if (dist < best_v[j] || (dist == best_v[j] && kg < best_k[j])) { best_v[j] = dist; best_k[j] = kg; }
                }
                {
                    int j = j2 * 2 + 1;
                    float dist = (e2k + z2v[j]) - 2.0f * d1;
                    if (dist < best_v[j] || (dist == best_v[j] && kg < best_k[j])) { best_v[j] = dist; best_k[j] = kg; }
                }
            }
        }
    }

    // cross-ty reduction (EsB region is dead now; alias as sval/sidx)
#pragma unroll
    for (int j = 0; j < 8; j++) {
        sval[ty * 128 + tx * 8 + j] = best_v[j];
        sidx[ty * 128 + tx * 8 + j] = best_k[j];
    }
    __syncthreads();
    if (tid < 128) {
        float bv = sval[tid];
        int bk = sidx[tid];
#pragma unroll
        for (int t = 1; t < 32; t++) {
            float v = sval[t * 128 + tid];
            int k2 = sidx[t * 128 + tid];
            if (v < bv || (v == bv && k2 < bk)) { bv = v; bk = k2; }
        }
        int n = n0 + tid;
        g_idx[b * NN + n] = bk;
        long long off = (long long)ZQ_SIZE + b * NN + n;
        if (off < (long long)out_size) dout[off] = (float)bk;
    }
}

// ---------- kernel 4: gather z_q via smem-staged E rows, loss partials ----------
__global__ void k_gather(const float* __restrict__ z, const float* __restrict__ E,
                         float* __restrict__ dout) {
    __shared__ float srow[32 * 257];   // 32 rows, 257-pad for conflict-free reads
    __shared__ int   skid[32];
    __shared__ float sw[8];
    int b = blockIdx.x >> 5, h = blockIdx.x & 31;
    int tid = threadIdx.x;
    int warp = tid >> 5, lane = tid & 31;

    if (tid < 32) skid[tid] = g_idx[b * NN + h * WW + tid];
    __syncthreads();

    // stage 32 E rows coalescedly: each warp loads 4 rows
#pragma unroll
    for (int r2 = 0; r2 < 4; r2++) {
        int r = warp * 4 + r2;
        const float* er = E + skid[r] * CC;
#pragma unroll
        for (int i = 0; i < 8; i++)
            srow[r * 257 + lane + 32 * i] = er[lane + 32 * i];
    }
    __syncthreads();

    // compute: lane = w, warp covers c-range [warp*32, warp*32+32)
    int w = lane;
    float local = 0.f;
#pragma unroll 4
    for (int s = 0; s < 32; s++) {
        int c = warp * 32 + s;
        long long zoff = ((long long)(b * CC + c) * HH + h) * WW + w;
        float zv = z[zoff];
        float eq = srow[w * 257 + c];
        float d = eq - zv;
        local = fmaf(d, d, local);
        dout[zoff] = eq;   // z_q_st == z_q numerically (straight-through)
    }
#pragma unroll
    for (int o = 16; o; o >>= 1) local += __shfl_xor_sync(0xFFFFFFFFu, local, o);
    if (lane == 0) sw[warp] = local;
    __syncthreads();
    if (tid == 0) {
        float s2 = 0.f;
#pragma unroll
        for (int i = 0; i < 8; i++) s2 += sw[i];
        g_losspart[blockIdx.x] = s2;
    }
}

// ---------- kernel 5: deterministic loss finalize ----------
__global__ void k_final(float* __restrict__ dout, int out_size) {
    __shared__ float smf[256];
    float s = 0.f;
    for (int i = threadIdx.x; i < 1024; i += 256) s += g_losspart[i];
    smf[threadIdx.x] = s;
    __syncthreads();
    if (threadIdx.x == 0) {
        float t = 0.f;
        for (int i = 0; i < 256; i++) t += smf[i];
        float m = t / 8388608.0f;                 // mean((z_q - z_p)^2)
        float loss = m + 0.25f * m;               // + BETA * same mean
        long long off = (long long)ZQ_SIZE + IDX_SIZE;
        if (off < (long long)out_size) dout[off] = loss;
    }
}

extern "C" void kernel_launch(void* const* d_in, const int* in_sizes, int n_in,
                              void* d_out, int out_size) {
    const float* z = (const float*)d_in[0];
    const float* E = (const float*)d_in[1];
    float* out = (float*)d_out;

    // Raise dynamic smem cap for the persistent-M GEMM (idempotent, capture-legal).
    cudaFuncSetAttribute(k_gemm, cudaFuncAttributeMaxDynamicSharedMemorySize, SMEM_BYTES);

    k_e2<<<128, 256>>>(E);
    k_tr<<<1024, 256>>>(z);
    k_gemm<<<256, 512, SMEM_BYTES>>>(E, out, out_size);
    if (out_size >= ZQ_SIZE) k_gather<<<1024, 256>>>(z, E, out);
    k_final<<<1, 256>>>(out, out_size);
}

// round 5
// speedup vs baseline: 1.1069x; 1.1069x over previous
#include <cuda_runtime.h>

// Problem constants
#define BB 32
#define CC 256
#define HH 32
#define WW 32
#define KK 1024
#define NN 1024                      // H*W
#define ZP_BATCH (CC * NN)           // 262144 floats per batch
#define ZQ_SIZE (BB * CC * HH * WW)  // 8388608
#define IDX_SIZE (BB * NN)           // 32768

typedef unsigned long long ull;

// Device scratch (allocation-free rule: __device__ globals)
__device__ float g_zp[BB * ZP_BATCH];   // z permuted to [b][h][w][c] contiguous
__device__ float g_e2[KK];              // ||E_k||^2
__device__ float g_z2[BB * NN];         // column norms of the reinterpreted Z view
__device__ int   g_idx[BB * NN];        // argmin indices
__device__ float g_losspart[1024];      // per-block loss partials (deterministic reduce)

// ---------- packed f32x2 helpers (sm_100+ PTX) ----------
__device__ __forceinline__ ull pack2(float lo, float hi) {
    ull r;
    asm("mov.b64 %0, {%1, %2};" : "=l"(r) : "f"(lo), "f"(hi));
    return r;
}
__device__ __forceinline__ void unpack2(ull v, float& lo, float& hi) {
    asm("mov.b64 {%0, %1}, %2;" : "=f"(lo), "=f"(hi) : "l"(v));
}
__device__ __forceinline__ void fma2(ull& d, ull a, ull b) {
    asm("fma.rn.f32x2 %0, %1, %2, %0;" : "+l"(d) : "l"(a), "l"(b));
}

// ---------- kernel 1: e2[k] = sum_c E[k][c]^2 (warp per k) ----------
__global__ void k_e2(const float* __restrict__ E) {
    int warp = threadIdx.x >> 5, lane = threadIdx.x & 31;
    int k = blockIdx.x * 8 + warp;   // 128 blocks * 8 warps = 1024
    const float* row = E + k * CC;
    float s = 0.f;
#pragma unroll
    for (int i = 0; i < 8; i++) { float v = row[lane + 32 * i]; s = fmaf(v, v, s); }
#pragma unroll
    for (int o = 16; o; o >>= 1) s += __shfl_xor_sync(0xFFFFFFFFu, s, o);
    if (lane == 0) g_e2[k] = s;
}

// ---------- kernel 2: transpose z[b,c,h,w] -> g_zp[b][h][w][c] ----------
__global__ void k_tr(const float* __restrict__ z) {
    __shared__ float s[CC][33];       // padded: conflict-free both phases
    int b = blockIdx.x >> 5, h = blockIdx.x & 31;
    int w = threadIdx.x & 31, t8 = threadIdx.x >> 5;  // t8 in [0,8)
    const float* zp = z + ((long long)(b * CC) * HH + h) * WW + w;
#pragma unroll
    for (int i = 0; i < 32; i++) {
        int c = t8 * 32 + i;
        s[c][w] = zp[(long long)c * HH * WW];
    }
    __syncthreads();
    float* out = g_zp + (long long)b * ZP_BATCH + h * (WW * CC);
#pragma unroll
    for (int i = 0; i < 32; i++) {
        int f = threadIdx.x + i * 256;     // 0..8191 contiguous output
        int c = f & 255, ww = f >> 8;
        out[f] = s[c][ww];
    }
}

// ---------- kernel 3: z2[b][n] = sum_i M[i][n]^2 over the [256,1024] view ----------
__global__ void k_z2() {
    int b = blockIdx.x >> 2;                    // 128 blocks
    int n = (blockIdx.x & 3) * 256 + threadIdx.x;
    const float* base = g_zp + (long long)b * ZP_BATCH + n;
    float s = 0.f;
#pragma unroll 8
    for (int i = 0; i < CC; i++) { float v = base[i * NN]; s = fmaf(v, v, s); }
    g_z2[b * NN + n] = s;
}

// ---------- kernel 4: fused GEMM (f32x2) + argmin ----------
// dist[k][n] = (e2[k] + z2[n]) - 2 * sum_c E[k][c] * M[c][n]
// 256 threads = (ty 16) x (tx 16), 2 CTAs/SM. Tile: 128 k x 128 n per slab, 8 slabs.
// Per slab: 32 chunks of 8 c cover the full C=256 reduction.
// Thread n-columns: n = tx*2 + j2*32 + {0,1} for j2 in 0..3 (conflict-free LDS.64 b-frags).
__global__ void __launch_bounds__(256, 2) k_gemm(const float* __restrict__ E,
                                                 float* __restrict__ dout, int out_size) {
    __shared__ float Ms[2][8][128];   // [buf][c][n]
    __shared__ ull   EsD[2][8][128];  // [buf][c][k] duplicated pairs (16 KB)
    float* sval = (float*)EsD;            // [16][128] alias (after main loop)
    int*   sidx = (int*)((float*)EsD + 2048);

    int tid = threadIdx.x;
    int ty = tid >> 4, tx = tid & 15;
    int b = blockIdx.x >> 3;
    int n0 = (blockIdx.x & 7) * 128;
    const float* Mb = g_zp + (long long)b * ZP_BATCH;

    // staging roles
    int ek = tid >> 1, ec4 = (tid & 1) * 4;   // E: 8c x 128k per chunk, float4/thread
    int mcc = tid >> 5, mnn = (tid & 31) * 4; // M: 8c x 128n per chunk, float4/thread

    // z2 for this thread's 8 n-columns (global, L1-cached, once)
    float z2v[8];
#pragma unroll
    for (int j = 0; j < 8; j++) {
        int n_loc = tx * 2 + (j >> 1) * 32 + (j & 1);
        z2v[j] = g_z2[b * NN + n0 + n_loc];
    }

    // prefetch + store chunk 0 (slab 0, c 0..7)
    float4 ef = *(const float4*)&E[ek * CC + ec4];
    float4 mf = *(const float4*)&Mb[mcc * NN + n0 + mnn];
    EsD[0][ec4 + 0][ek] = pack2(ef.x, ef.x);
    EsD[0][ec4 + 1][ek] = pack2(ef.y, ef.y);
    EsD[0][ec4 + 2][ek] = pack2(ef.z, ef.z);
    EsD[0][ec4 + 3][ek] = pack2(ef.w, ef.w);
    *(float4*)&Ms[0][mcc][mnn] = mf;
    __syncthreads();

    float best_v[8];
    int   best_k[8];
#pragma unroll
    for (int j = 0; j < 8; j++) { best_v[j] = 3.4e38f; best_k[j] = 0; }

    int buf = 0;
    for (int ko = 0; ko < 8; ko++) {       // k-slab of 128
        ull acc[8][4];
#pragma unroll
        for (int i = 0; i < 8; i++)
#pragma unroll
            for (int j = 0; j < 4; j++) acc[i][j] = 0ull;

        for (int ch = 0; ch < 32; ch++) {  // c-chunk of 8: 32 chunks = full C=256
            int q = ko * 32 + ch;
            bool more = (q + 1 < 256);
            if (more) {
                int nk0 = ((q + 1) >> 5) * 128, nc0 = ((q + 1) & 31) * 8;
                ef = *(const float4*)&E[(nk0 + ek) * CC + nc0 + ec4];
                mf = *(const float4*)&Mb[(nc0 + mcc) * NN + n0 + mnn];
            }
#pragma unroll 4
            for (int cc = 0; cc < 8; cc++) {
                const ull* pb = (const ull*)&Ms[buf][cc][0];
                ull b0 = pb[tx], b1 = pb[tx + 16], b2 = pb[tx + 32], b3 = pb[tx + 48];
                const ull* pa = &EsD[buf][cc][ty * 8];
#pragma unroll
                for (int i = 0; i < 8; i++) {
                    ull ad = pa[i];
                    fma2(acc[i][0], ad, b0);
                    fma2(acc[i][1], ad, b1);
                    fma2(acc[i][2], ad, b2);
                    fma2(acc[i][3], ad, b3);
                }
            }
            if (more) {
                int nb = buf ^ 1;
                EsD[nb][ec4 + 0][ek] = pack2(ef.x, ef.x);
                EsD[nb][ec4 + 1][ek] = pack2(ef.y, ef.y);
                EsD[nb][ec4 + 2][ek] = pack2(ef.z, ef.z);
                EsD[nb][ec4 + 3][ek] = pack2(ef.w, ef.w);
                *(float4*)&Ms[nb][mcc][mnn] = mf;
            }
            __syncthreads();
            buf ^= 1;
        }

        // fold slab into running argmin (first-min tie-break via k compare)
        int k0 = ko * 128;
#pragma unroll
        for (int i = 0; i < 8; i++) {
            int kg = k0 + ty * 8 + i;
            float e2k = g_e2[kg];
#pragma unroll
            for (int j2 = 0; j2 < 4; j2++) {
                float d0, d1;
                unpack2(acc[i][j2], d0, d1);
                {
                    int j = j2 * 2;
                    float dist = (e2k + z2v[j]) - 2.0f * d0;
                    if (dist < best_v[j] || (dist == best_v[j] && kg < best_k[j])) { best_v[j] = dist; best_k[j] = kg; }
                }
                {
                    int j = j2 * 2 + 1;
                    float dist = (e2k + z2v[j]) - 2.0f * d1;
                    if (dist < best_v[j] || (dist == best_v[j] && kg < best_k[j])) { best_v[j] = dist; best_k[j] = kg; }
                }
            }
        }
    }

    // cross-ty reduction (EsD dead: alias as sval/sidx)
#pragma unroll
    for (int j = 0; j < 8; j++) {
        int n_loc = tx * 2 + (j >> 1) * 32 + (j & 1);
        sval[ty * 128 + n_loc] = best_v[j];
        sidx[ty * 128 + n_loc] = best_k[j];
    }
    __syncthreads();
    if (tid < 128) {
        float bv = sval[tid];
        int bk = sidx[tid];
#pragma unroll
        for (int t = 1; t < 16; t++) {
            float v = sval[t * 128 + tid];
            int k2 = sidx[t * 128 + tid];
            if (v < bv || (v == bv && k2 < bk)) { bv = v; bk = k2; }
        }
        int n = n0 + tid;
        g_idx[b * NN + n] = bk;
        long long off = (long long)ZQ_SIZE + b * NN + n;
        if (off < (long long)out_size) dout[off] = (float)bk;
    }
}

// ---------- kernel 5: gather z_q via smem-staged E rows, loss partials ----------
__global__ void k_gather(const float* __restrict__ z, const float* __restrict__ E,
                         float* __restrict__ dout) {
    __shared__ float srow[32 * 257];   // 32 rows, 257-pad for conflict-free reads
    __shared__ int   skid[32];
    __shared__ float sw[8];
    int b = blockIdx.x >> 5, h = blockIdx.x & 31;
    int tid = threadIdx.x;
    int warp = tid >> 5, lane = tid & 31;

    if (tid < 32) skid[tid] = g_idx[b * NN + h * WW + tid];
    __syncthreads();

    // stage 32 E rows coalescedly: each warp loads 4 rows
#pragma unroll
    for (int r2 = 0; r2 < 4; r2++) {
        int r = warp * 4 + r2;
        const float* er = E + skid[r] * CC;
#pragma unroll
        for (int i = 0; i < 8; i++)
            srow[r * 257 + lane + 32 * i] = er[lane + 32 * i];
    }
    __syncthreads();

    // compute: lane = w, warp covers c-range [warp*32, warp*32+32)
    int w = lane;
    float local = 0.f;
#pragma unroll 4
    for (int s = 0; s < 32; s++) {
        int c = warp * 32 + s;
        long long zoff = ((long long)(b * CC + c) * HH + h) * WW + w;
        float zv = z[zoff];
        float eq = srow[w * 257 + c];
        float d = eq - zv;
        local = fmaf(d, d, local);
        dout[zoff] = eq;   // z_q_st == z_q numerically (straight-through)
    }
#pragma unroll
    for (int o = 16; o; o >>= 1) local += __shfl_xor_sync(0xFFFFFFFFu, local, o);
    if (lane == 0) sw[warp] = local;
    __syncthreads();
    if (tid == 0) {
        float s2 = 0.f;
#pragma unroll
        for (int i = 0; i < 8; i++) s2 += sw[i];
        g_losspart[blockIdx.x] = s2;
    }
}

// ---------- kernel 6: deterministic loss finalize ----------
__global__ void k_final(float* __restrict__ dout, int out_size) {
    __shared__ float smf[256];
    float s = 0.f;
    for (int i = threadIdx.x; i < 1024; i += 256) s += g_losspart[i];
    smf[threadIdx.x] = s;
    __syncthreads();
    if (threadIdx.x == 0) {
        float t = 0.f;
        for (int i = 0; i < 256; i++) t += smf[i];
        float m = t / 8388608.0f;                 // mean((z_q - z_p)^2)
        float loss = m + 0.25f * m;               // + BETA * same mean
        long long off = (long long)ZQ_SIZE + IDX_SIZE;
        if (off < (long long)out_size) dout[off] = loss;
    }
}

extern "C" void kernel_launch(void* const* d_in, const int* in_sizes, int n_in,
                              void* d_out, int out_size) {
    const float* z = (const float*)d_in[0];
    const float* E = (const float*)d_in[1];
    float* out = (float*)d_out;

    k_e2<<<128, 256>>>(E);
    k_tr<<<1024, 256>>>(z);
    k_z2<<<128, 256>>>();
    k_gemm<<<256, 256>>>(E, out, out_size);
    if (out_size >= ZQ_SIZE) k_gather<<<1024, 256>>>(z, E, out);
    k_final<<<1, 256>>>(out, out_size);
}

// round 8
// speedup vs baseline: 2.4493x; 2.2128x over previous
#include <cuda_runtime.h>
#include <cuda_fp16.h>
#include <cstdint>

// Problem constants
#define BB 32
#define CC 256
#define HH 32
#define WW 32
#define KK 1024
#define NN 1024                      // H*W
#define ZP_BATCH (CC * NN)           // 262144 floats per batch
#define ZQ_SIZE (BB * CC * HH * WW)  // 8388608
#define IDX_SIZE (BB * NN)           // 32768

// ---------------- k_mma smem layout (u32 units) ----------------
// Apack hi [128 c2][136 pad]  @ 0
// Apack lo                    @ OFF_ALO
// E bufs [2 buf][hi/lo][128 k][20 pad] @ OFF_EB
// e2s (float[1024])           @ OFF_E2
#define AST 136
#define EST 20
#define OFF_ALO (128 * AST)               // 17408
#define OFF_EB  (2 * 128 * AST)           // 34816
#define EB_SEG  (128 * EST)               // 2560
#define OFF_E2  (OFF_EB + 4 * EB_SEG)     // 45056
#define SMEM_U32 (OFF_E2 + 1024)          // 46080
#define SMEM_MMA_BYTES (SMEM_U32 * 4)     // 184320

#define INV2048 4.8828125e-4f

// Device scratch (allocation-free rule: __device__ globals)
__device__ float g_zp[BB * ZP_BATCH];   // contiguous [b][h][w][c] image of z_p
__device__ float g_e2[KK];
__device__ float g_z2[BB * NN];         // view-column norms
__device__ int   g_idx[BB * NN];
__device__ float g_losspart[1024];

// ---------- helpers ----------
__device__ __forceinline__ uint32_t h2u(__half a, __half b) {
    __half2 t = __halves2half2(a, b);
    return *(uint32_t*)&t;
}
__device__ __forceinline__ __half lo_split(float x, __half h) {
    return __float2half_rn((x - __half2float(h)) * 2048.0f);
}
__device__ __forceinline__ void mma_f16(float* d, uint32_t a0, uint32_t a1,
                                        uint32_t a2, uint32_t a3,
                                        uint32_t b0, uint32_t b1) {
    asm volatile(
        "mma.sync.aligned.m16n8k16.row.col.f32.f16.f16.f32 "
        "{%0,%1,%2,%3}, {%4,%5,%6,%7}, {%8,%9}, {%0,%1,%2,%3};"
        : "+f"(d[0]), "+f"(d[1]), "+f"(d[2]), "+f"(d[3])
        : "r"(a0), "r"(a1), "r"(a2), "r"(a3), "r"(b0), "r"(b1));
}

// ---------- kernel 1: e2[k] = sum_c E[k][c]^2 ----------
__global__ void k_e2(const float* __restrict__ E) {
    int warp = threadIdx.x >> 5, lane = threadIdx.x & 31;
    int k = blockIdx.x * 8 + warp;
    const float* row = E + k * CC;
    float s = 0.f;
#pragma unroll
    for (int i = 0; i < 8; i++) { float v = row[lane + 32 * i]; s = fmaf(v, v, s); }
#pragma unroll
    for (int o = 16; o; o >>= 1) s += __shfl_xor_sync(0xFFFFFFFFu, s, o);
    if (lane == 0) g_e2[k] = s;
}

// ---------- kernel 2: transpose z[b,c,h,w] -> g_zp = contiguous [b,h,w,c] ----------
__global__ void k_tr(const float* __restrict__ z) {
    __shared__ float s[CC][33];
    int b = blockIdx.x >> 5, h = blockIdx.x & 31;
    int w = threadIdx.x & 31, t8 = threadIdx.x >> 5;
    const float* zp = z + ((long long)(b * CC) * HH + h) * WW + w;
#pragma unroll
    for (int i = 0; i < 32; i++) {
        int c = t8 * 32 + i;
        s[c][w] = zp[(long long)c * HH * WW];
    }
    __syncthreads();
    float* out = g_zp + (long long)b * ZP_BATCH + h * (WW * CC);
#pragma unroll
    for (int i = 0; i < 32; i++) {
        int f = threadIdx.x + i * 256;
        int c = f & 255, ww = f >> 8;
        out[f] = s[c][ww];
    }
}

// ---------- kernel 3: z2[b][n] over the REINTERPRETED [256,1024] view ----------
__global__ void k_z2() {
    int b = blockIdx.x >> 2;
    int n = (blockIdx.x & 3) * 256 + threadIdx.x;
    const float* base = g_zp + (long long)b * ZP_BATCH + n;
    float s = 0.f;
#pragma unroll 8
    for (int i = 0; i < CC; i++) { float v = base[i * NN]; s = fmaf(v, v, s); }
    g_z2[b * NN + n] = s;
}

// ---------- kernel 4: fp16 2-split mma.sync GEMM + argmin ----------
// View matrix M[c][n] = flat[c*1024+n].  dist[k][n] = (e2[k]+z2[n]) - 2*dot.
// CTA: 128 view-cols (n0..n0+127) x all 1024 codes. Warp w owns cols [16w,16w+16).
__global__ void __launch_bounds__(256, 1) k_mma(const float* __restrict__ E,
                                                float* __restrict__ dout, int out_size) {
    extern __shared__ uint32_t smu[];
    uint32_t* AhU = smu;
    uint32_t* AlU = smu + OFF_ALO;
    float* e2s = (float*)(smu + OFF_E2);

    int tid = threadIdx.x;
    int w = tid >> 5, lane = tid & 31;
    int g = lane >> 2, t = lane & 3;
    int b = blockIdx.x >> 3;
    int n0 = (blockIdx.x & 7) * 128;
    const float* Mb = g_zp + (long long)b * ZP_BATCH;   // flat buffer

    // ---- stage A panel: Apack[c2][p] = half2(flat[2c2*NN+n0+p], flat[(2c2+1)*NN+n0+p]) ----
#pragma unroll 2
    for (int i = 0; i < 16; i++) {
        int c2 = w * 16 + i;
        const float* r0 = Mb + (long long)(2 * c2) * NN + n0;
        const float* r1 = r0 + NN;
        float4 va = *(const float4*)&r0[lane * 4];
        float4 vb = *(const float4*)&r1[lane * 4];
        __half ha0 = __float2half_rn(va.x), ha1 = __float2half_rn(va.y);
        __half ha2 = __float2half_rn(va.z), ha3 = __float2half_rn(va.w);
        __half hb0 = __float2half_rn(vb.x), hb1 = __float2half_rn(vb.y);
        __half hb2 = __float2half_rn(vb.z), hb3 = __float2half_rn(vb.w);
        uint4 hv = make_uint4(h2u(ha0, hb0), h2u(ha1, hb1), h2u(ha2, hb2), h2u(ha3, hb3));
        uint4 lv = make_uint4(h2u(lo_split(va.x, ha0), lo_split(vb.x, hb0)),
                              h2u(lo_split(va.y, ha1), lo_split(vb.y, hb1)),
                              h2u(lo_split(va.z, ha2), lo_split(vb.z, hb2)),
                              h2u(lo_split(va.w, ha3), lo_split(vb.w, hb3)));
        *(uint4*)&AhU[c2 * AST + lane * 4] = hv;
        *(uint4*)&AlU[c2 * AST + lane * 4] = lv;
    }
    for (int i = tid; i < KK; i += 256) e2s[i] = g_e2[i];

    // ---- E staging roles ----
    int erow = tid >> 1;               // k-local 0..127
    int cfl = (tid & 1) * 16;          // float offset within 32-c chunk
    int c2seg = (tid & 1) * 8;         // c2 offset
    float4 pre[4];
#pragma unroll
    for (int i = 0; i < 4; i++)
        pre[i] = *(const float4*)&E[erow * CC + cfl + i * 4];   // chunk 0
    {
        uint32_t* Eh = smu + OFF_EB + erow * EST + c2seg;       // buf0 hi
        uint32_t* El = Eh + EB_SEG;
#pragma unroll
        for (int i = 0; i < 4; i++) {
            float4 v = pre[i];
            __half hx = __float2half_rn(v.x), hy = __float2half_rn(v.y);
            __half hz = __float2half_rn(v.z), hw2 = __float2half_rn(v.w);
            Eh[2 * i] = h2u(hx, hy); Eh[2 * i + 1] = h2u(hz, hw2);
            El[2 * i] = h2u(lo_split(v.x, hx), lo_split(v.y, hy));
            El[2 * i + 1] = h2u(lo_split(v.z, hz), lo_split(v.w, hw2));
        }
    }

    int p0 = w * 16 + g, p1 = p0 + 8;
    float z2a = g_z2[b * NN + n0 + p0];
    float z2b = g_z2[b * NN + n0 + p1];
    float bv0 = 3.4e38f, bv1 = 3.4e38f;
    int   bk0 = 0, bk1 = 0;
    __syncthreads();

    float acc_hh[16][4], acc_lo[16][4];

    for (int q = 0; q < 64; q++) {             // chunk: k-slab q>>3, c-range (q&7)*32
        int buf = q & 1, ch = q & 7;
        if (ch == 0) {
#pragma unroll
            for (int nf = 0; nf < 16; nf++)
#pragma unroll
                for (int j = 0; j < 4; j++) { acc_hh[nf][j] = 0.f; acc_lo[nf][j] = 0.f; }
        }
        if (q + 1 < 64) {
            int nk0 = ((q + 1) >> 3) * 128, nc0 = ((q + 1) & 7) * 32;
#pragma unroll
            for (int i = 0; i < 4; i++)
                pre[i] = *(const float4*)&E[(nk0 + erow) * CC + nc0 + cfl + i * 4];
        }

        const uint32_t* Eh = smu + OFF_EB + (buf * 2) * EB_SEG;
        const uint32_t* El = Eh + EB_SEG;
#pragma unroll
        for (int s = 0; s < 2; s++) {
            int c2b = ch * 16 + s * 8;
            uint32_t ah0 = AhU[(c2b + t) * AST + p0];
            uint32_t ah1 = AhU[(c2b + t) * AST + p1];
            uint32_t ah2 = AhU[(c2b + t + 4) * AST + p0];
            uint32_t ah3 = AhU[(c2b + t + 4) * AST + p1];
            uint32_t al0 = AlU[(c2b + t) * AST + p0];
            uint32_t al1 = AlU[(c2b + t) * AST + p1];
            uint32_t al2 = AlU[(c2b + t + 4) * AST + p0];
            uint32_t al3 = AlU[(c2b + t + 4) * AST + p1];
            int c2l = s * 8;
#pragma unroll
            for (int nf = 0; nf < 16; nf++) {
                int krow = (nf * 8 + g) * EST + c2l;
                uint32_t bh0 = Eh[krow + t], bh1 = Eh[krow + t + 4];
                uint32_t bl0 = El[krow + t], bl1 = El[krow + t + 4];
                mma_f16(acc_hh[nf], ah0, ah1, ah2, ah3, bh0, bh1);
                mma_f16(acc_lo[nf], ah0, ah1, ah2, ah3, bl0, bl1);
                mma_f16(acc_lo[nf], al0, al1, al2, al3, bh0, bh1);
            }
        }

        if (ch == 7) {                          // slab done: fold argmin
            int k0 = (q >> 3) * 128;
#pragma unroll
            for (int nf = 0; nf < 16; nf++) {
                int ka = k0 + nf * 8 + 2 * t;
                float e2a = e2s[ka], e2b = e2s[ka + 1];
                float dot0 = fmaf(acc_lo[nf][0], INV2048, acc_hh[nf][0]);
                float dot1 = fmaf(acc_lo[nf][1], INV2048, acc_hh[nf][1]);
                float dot2 = fmaf(acc_lo[nf][2], INV2048, acc_hh[nf][2]);
                float dot3 = fmaf(acc_lo[nf][3], INV2048, acc_hh[nf][3]);
                float d0 = (e2a + z2a) - 2.0f * dot0;
                float d1 = (e2b + z2a) - 2.0f * dot1;
                float d2 = (e2a + z2b) - 2.0f * dot2;
                float d3 = (e2b + z2b) - 2.0f * dot3;
                if (d0 < bv0 || (d0 == bv0 && ka     < bk0)) { bv0 = d0; bk0 = ka; }
                if (d1 < bv0 || (d1 == bv0 && ka + 1 < bk0)) { bv0 = d1; bk0 = ka + 1; }
                if (d2 < bv1 || (d2 == bv1 && ka     < bk1)) { bv1 = d2; bk1 = ka; }
                if (d3 < bv1 || (d3 == bv1 && ka + 1 < bk1)) { bv1 = d3; bk1 = ka + 1; }
            }
        }

        if (q + 1 < 64) {
            uint32_t* EhN = smu + OFF_EB + ((buf ^ 1) * 2) * EB_SEG + erow * EST + c2seg;
            uint32_t* ElN = EhN + EB_SEG;
#pragma unroll
            for (int i = 0; i < 4; i++) {
                float4 v = pre[i];
                __half hx = __float2half_rn(v.x), hy = __float2half_rn(v.y);
                __half hz = __float2half_rn(v.z), hw2 = __float2half_rn(v.w);
                EhN[2 * i] = h2u(hx, hy); EhN[2 * i + 1] = h2u(hz, hw2);
                ElN[2 * i] = h2u(lo_split(v.x, hx), lo_split(v.y, hy));
                ElN[2 * i + 1] = h2u(lo_split(v.z, hz), lo_split(v.w, hw2));
            }
        }
        __syncthreads();
    }

    // reduce over the 4 lanes of each group (lexicographic, first-k preference)
#pragma unroll
    for (int off = 1; off <= 2; off <<= 1) {
        float ov0 = __shfl_xor_sync(0xFFFFFFFFu, bv0, off);
        int   ok0 = __shfl_xor_sync(0xFFFFFFFFu, bk0, off);
        float ov1 = __shfl_xor_sync(0xFFFFFFFFu, bv1, off);
        int   ok1 = __shfl_xor_sync(0xFFFFFFFFu, bk1, off);
        if (ov0 < bv0 || (ov0 == bv0 && ok0 < bk0)) { bv0 = ov0; bk0 = ok0; }
        if (ov1 < bv1 || (ov1 == bv1 && ok1 < bk1)) { bv1 = ov1; bk1 = ok1; }
    }
    if (t == 0) {
        int na = n0 + p0, nb = n0 + p1;
        g_idx[b * NN + na] = bk0;
        g_idx[b * NN + nb] = bk1;
        long long offa = (long long)ZQ_SIZE + b * NN + na;
        long long offb = (long long)ZQ_SIZE + b * NN + nb;
        if (offa < (long long)out_size) dout[offa] = (float)bk0;
        if (offb < (long long)out_size) dout[offb] = (float)bk1;
    }
}

// ---------- kernel 5: gather z_q (STE-exact), loss partials ----------
__global__ void k_gather(const float* __restrict__ z, const float* __restrict__ E,
                         float* __restrict__ dout) {
    __shared__ float srow[32 * 257];
    __shared__ int   skid[32];
    __shared__ float sw[8];
    int b = blockIdx.x >> 5, h = blockIdx.x & 31;
    int tid = threadIdx.x;
    int warp = tid >> 5, lane = tid & 31;

    if (tid < 32) skid[tid] = g_idx[b * NN + h * WW + tid];
    __syncthreads();

#pragma unroll
    for (int r2 = 0; r2 < 4; r2++) {
        int r = warp * 4 + r2;
        const float* er = E + skid[r] * CC;
#pragma unroll
        for (int i = 0; i < 8; i++)
            srow[r * 257 + lane + 32 * i] = er[lane + 32 * i];
    }
    __syncthreads();

    int w = lane;
    float local = 0.f;
#pragma unroll 4
    for (int s = 0; s < 32; s++) {
        int c = warp * 32 + s;
        long long zoff = ((long long)(b * CC + c) * HH + h) * WW + w;
        float zv = z[zoff];
        float eq = srow[w * 257 + c];
        float d = eq - zv;
        local = fmaf(d, d, local);
        dout[zoff] = zv + (eq - zv);   // exact straight-through arithmetic
    }
#pragma unroll
    for (int o = 16; o; o >>= 1) local += __shfl_xor_sync(0xFFFFFFFFu, local, o);
    if (lane == 0) sw[warp] = local;
    __syncthreads();
    if (tid == 0) {
        float s2 = 0.f;
#pragma unroll
        for (int i = 0; i < 8; i++) s2 += sw[i];
        g_losspart[blockIdx.x] = s2;
    }
}

// ---------- kernel 6: deterministic loss finalize ----------
__global__ void k_final(float* __restrict__ dout, int out_size) {
    __shared__ float smf[256];
    float s = 0.f;
    for (int i = threadIdx.x; i < 1024; i += 256) s += g_losspart[i];
    smf[threadIdx.x] = s;
    __syncthreads();
    if (threadIdx.x == 0) {
        float t = 0.f;
        for (int i = 0; i < 256; i++) t += smf[i];
        float m = t / 8388608.0f;
        float loss = m + 0.25f * m;
        long long off = (long long)ZQ_SIZE + IDX_SIZE;
        if (off < (long long)out_size) dout[off] = loss;
    }
}

extern "C" void kernel_launch(void* const* d_in, const int* in_sizes, int n_in,
                              void* d_out, int out_size) {
    const float* z = (const float*)d_in[0];
    const float* E = (const float*)d_in[1];
    float* out = (float*)d_out;

    cudaFuncSetAttribute(k_mma, cudaFuncAttributeMaxDynamicSharedMemorySize, SMEM_MMA_BYTES);

    k_e2<<<128, 256>>>(E);
    k_tr<<<1024, 256>>>(z);
    k_z2<<<128, 256>>>();
    k_mma<<<256, 256, SMEM_MMA_BYTES>>>(E, out, out_size);
    if (out_size >= ZQ_SIZE) k_gather<<<1024, 256>>>(z, E, out);
    k_final<<<1, 256>>>(out, out_size);
}

// round 9
// speedup vs baseline: 2.5182x; 1.0282x over previous
#include <cuda_runtime.h>
#include <cuda_fp16.h>
#include <cstdint>

// Problem constants
#define BB 32
#define CC 256
#define HH 32
#define WW 32
#define KK 1024
#define NN 1024                      // H*W
#define ZP_BATCH (CC * NN)           // 262144 floats per batch
#define ZQ_SIZE (BB * CC * HH * WW)  // 8388608
#define IDX_SIZE (BB * NN)           // 32768

// ---------------- k_mma smem layout (u32 units) ----------------
#define AST 136
#define EST 20
#define OFF_ALO (128 * AST)               // 17408
#define OFF_EB  (2 * 128 * AST)           // 34816
#define EB_SEG  (128 * EST)               // 2560
#define OFF_E2  (OFF_EB + 4 * EB_SEG)     // 45056
#define SMEM_U32 (OFF_E2 + 1024)          // 46080
#define SMEM_MMA_BYTES (SMEM_U32 * 4)     // 184320

#define INV2048 4.8828125e-4f

// Device scratch (allocation-free rule: __device__ globals)
__device__ float g_zp[BB * ZP_BATCH];   // contiguous [b][h][w][c] image of z_p
__device__ float g_e2[KK];
__device__ float g_z2[BB * NN];         // view-column norms
__device__ int   g_idx[BB * NN];
__device__ float g_losspart[1024];

// ---------- helpers ----------
__device__ __forceinline__ uint32_t h2u(__half a, __half b) {
    __half2 t = __halves2half2(a, b);
    return *(uint32_t*)&t;
}
__device__ __forceinline__ __half lo_split(float x, __half h) {
    return __float2half_rn((x - __half2float(h)) * 2048.0f);
}
__device__ __forceinline__ void mma_f16(float* d, uint32_t a0, uint32_t a1,
                                        uint32_t a2, uint32_t a3,
                                        uint32_t b0, uint32_t b1) {
    asm volatile(
        "mma.sync.aligned.m16n8k16.row.col.f32.f16.f16.f32 "
        "{%0,%1,%2,%3}, {%4,%5,%6,%7}, {%8,%9}, {%0,%1,%2,%3};"
        : "+f"(d[0]), "+f"(d[1]), "+f"(d[2]), "+f"(d[3])
        : "r"(a0), "r"(a1), "r"(a2), "r"(a3), "r"(b0), "r"(b1));
}

// ---------- kernel 1: e2[k] = sum_c E[k][c]^2 ----------
__global__ void k_e2(const float* __restrict__ E) {
    int warp = threadIdx.x >> 5, lane = threadIdx.x & 31;
    int k = blockIdx.x * 8 + warp;
    const float* row = E + k * CC;
    float s = 0.f;
#pragma unroll
    for (int i = 0; i < 8; i++) { float v = row[lane + 32 * i]; s = fmaf(v, v, s); }
#pragma unroll
    for (int o = 16; o; o >>= 1) s += __shfl_xor_sync(0xFFFFFFFFu, s, o);
    if (lane == 0) g_e2[k] = s;
}

// ---------- kernel 2: transpose z[b,c,h,w] -> g_zp = contiguous [b,h,w,c] ----------
__global__ void k_tr(const float* __restrict__ z) {
    __shared__ float s[CC][33];
    int b = blockIdx.x >> 5, h = blockIdx.x & 31;
    int w = threadIdx.x & 31, t8 = threadIdx.x >> 5;
    const float* zp = z + ((long long)(b * CC) * HH + h) * WW + w;
#pragma unroll
    for (int i = 0; i < 32; i++) {
        int c = t8 * 32 + i;
        s[c][w] = zp[(long long)c * HH * WW];
    }
    __syncthreads();
    float* out = g_zp + (long long)b * ZP_BATCH + h * (WW * CC);
#pragma unroll
    for (int i = 0; i < 32; i++) {
        int f = threadIdx.x + i * 256;
        int c = f & 255, ww = f >> 8;
        out[f] = s[c][ww];
    }
}

// ---------- kernel 3: z2[b][n] over the REINTERPRETED [256,1024] view ----------
__global__ void k_z2() {
    int b = blockIdx.x >> 2;
    int n = (blockIdx.x & 3) * 256 + threadIdx.x;
    const float* base = g_zp + (long long)b * ZP_BATCH + n;
    float s = 0.f;
#pragma unroll 8
    for (int i = 0; i < CC; i++) { float v = base[i * NN]; s = fmaf(v, v, s); }
    g_z2[b * NN + n] = s;
}

// ---------- kernel 4: fp16 2-split mma.sync GEMM + argmin (512 thr, 16 warps) ----------
// View matrix M[c][n] = flat[c*1024+n].  dist[k][n] = (e2[k]+z2[n]) - 2*dot.
// Warp (wr = w>>3, wp = w&7): pixels [16wp, 16wp+16), half-slab nf = wr*8 + [0,8).
__global__ void __launch_bounds__(512, 1) k_mma(const float* __restrict__ E,
                                                float* __restrict__ dout, int out_size) {
    extern __shared__ uint32_t smu[];
    uint32_t* AhU = smu;
    uint32_t* AlU = smu + OFF_ALO;
    float* e2s = (float*)(smu + OFF_E2);

    int tid = threadIdx.x;
    int w = tid >> 5, lane = tid & 31;
    int g = lane >> 2, t = lane & 3;
    int wr = w >> 3, wp = w & 7;
    int b = blockIdx.x >> 3;
    int n0 = (blockIdx.x & 7) * 128;
    const float* Mb = g_zp + (long long)b * ZP_BATCH;   // flat buffer

    // ---- stage A panel: Apack[c2][p] = half2(flat[2c2*NN+n0+p], flat[(2c2+1)*NN+n0+p]) ----
#pragma unroll 2
    for (int i = 0; i < 8; i++) {
        int c2 = w * 8 + i;                    // 16 warps x 8 = 128 c2-rows
        const float* r0 = Mb + (long long)(2 * c2) * NN + n0;
        const float* r1 = r0 + NN;
        float4 va = *(const float4*)&r0[lane * 4];
        float4 vb = *(const float4*)&r1[lane * 4];
        __half ha0 = __float2half_rn(va.x), ha1 = __float2half_rn(va.y);
        __half ha2 = __float2half_rn(va.z), ha3 = __float2half_rn(va.w);
        __half hb0 = __float2half_rn(vb.x), hb1 = __float2half_rn(vb.y);
        __half hb2 = __float2half_rn(vb.z), hb3 = __float2half_rn(vb.w);
        uint4 hv = make_uint4(h2u(ha0, hb0), h2u(ha1, hb1), h2u(ha2, hb2), h2u(ha3, hb3));
        uint4 lv = make_uint4(h2u(lo_split(va.x, ha0), lo_split(vb.x, hb0)),
                              h2u(lo_split(va.y, ha1), lo_split(vb.y, hb1)),
                              h2u(lo_split(va.z, ha2), lo_split(vb.z, hb2)),
                              h2u(lo_split(va.w, ha3), lo_split(vb.w, hb3)));
        *(uint4*)&AhU[c2 * AST + lane * 4] = hv;
        *(uint4*)&AlU[c2 * AST + lane * 4] = lv;
    }
    for (int i = tid; i < KK; i += 512) e2s[i] = g_e2[i];

    // ---- E staging roles: 512 threads, 8 floats each per chunk ----
    int erow = tid >> 2;               // k-local 0..127
    int cfl = (tid & 3) * 8;           // float offset within 32-c chunk
    int c2seg = (tid & 3) * 4;         // c2 offset
    float4 pre0, pre1;
    pre0 = *(const float4*)&E[erow * CC + cfl];
    pre1 = *(const float4*)&E[erow * CC + cfl + 4];
    {
        uint32_t* Eh = smu + OFF_EB + erow * EST + c2seg;       // buf0 hi
        uint32_t* El = Eh + EB_SEG;
        __half hx = __float2half_rn(pre0.x), hy = __float2half_rn(pre0.y);
        __half hz = __float2half_rn(pre0.z), hw2 = __float2half_rn(pre0.w);
        Eh[0] = h2u(hx, hy); Eh[1] = h2u(hz, hw2);
        El[0] = h2u(lo_split(pre0.x, hx), lo_split(pre0.y, hy));
        El[1] = h2u(lo_split(pre0.z, hz), lo_split(pre0.w, hw2));
        hx = __float2half_rn(pre1.x); hy = __float2half_rn(pre1.y);
        hz = __float2half_rn(pre1.z); hw2 = __float2half_rn(pre1.w);
        Eh[2] = h2u(hx, hy); Eh[3] = h2u(hz, hw2);
        El[2] = h2u(lo_split(pre1.x, hx), lo_split(pre1.y, hy));
        El[3] = h2u(lo_split(pre1.z, hz), lo_split(pre1.w, hw2));
    }

    int p0 = wp * 16 + g, p1 = p0 + 8;
    float z2a = g_z2[b * NN + n0 + p0];
    float z2b = g_z2[b * NN + n0 + p1];
    float bv0 = 3.4e38f, bv1 = 3.4e38f;
    int   bk0 = 0, bk1 = 0;
    __syncthreads();

    float acc_hh[8][4], acc_lo[8][4];

    for (int q = 0; q < 64; q++) {             // chunk: k-slab q>>3, c-range (q&7)*32
        int buf = q & 1, ch = q & 7;
        if (ch == 0) {
#pragma unroll
            for (int nf = 0; nf < 8; nf++)
#pragma unroll
                for (int j = 0; j < 4; j++) { acc_hh[nf][j] = 0.f; acc_lo[nf][j] = 0.f; }
        }
        if (q + 1 < 64) {
            int nk0 = ((q + 1) >> 3) * 128, nc0 = ((q + 1) & 7) * 32;
            pre0 = *(const float4*)&E[(nk0 + erow) * CC + nc0 + cfl];
            pre1 = *(const float4*)&E[(nk0 + erow) * CC + nc0 + cfl + 4];
        }

        const uint32_t* Eh = smu + OFF_EB + (buf * 2) * EB_SEG;
        const uint32_t* El = Eh + EB_SEG;
#pragma unroll
        for (int s = 0; s < 2; s++) {
            int c2b = ch * 16 + s * 8;
            uint32_t ah0 = AhU[(c2b + t) * AST + p0];
            uint32_t ah1 = AhU[(c2b + t) * AST + p1];
            uint32_t ah2 = AhU[(c2b + t + 4) * AST + p0];
            uint32_t ah3 = AhU[(c2b + t + 4) * AST + p1];
            uint32_t al0 = AlU[(c2b + t) * AST + p0];
            uint32_t al1 = AlU[(c2b + t) * AST + p1];
            uint32_t al2 = AlU[(c2b + t + 4) * AST + p0];
            uint32_t al3 = AlU[(c2b + t + 4) * AST + p1];
            int c2l = s * 8;
#pragma unroll
            for (int nf = 0; nf < 8; nf++) {
                int krow = ((wr * 8 + nf) * 8 + g) * EST + c2l;
                uint32_t bh0 = Eh[krow + t], bh1 = Eh[krow + t + 4];
                uint32_t bl0 = El[krow + t], bl1 = El[krow + t + 4];
                mma_f16(acc_hh[nf], ah0, ah1, ah2, ah3, bh0, bh1);
                mma_f16(acc_lo[nf], ah0, ah1, ah2, ah3, bl0, bl1);
                mma_f16(acc_lo[nf], al0, al1, al2, al3, bh0, bh1);
            }
        }

        if (ch == 7) {                          // half-slab done: fold argmin
            int k0 = (q >> 3) * 128;
#pragma unroll
            for (int nf = 0; nf < 8; nf++) {
                int ka = k0 + (wr * 8 + nf) * 8 + 2 * t;
                float e2a = e2s[ka], e2b = e2s[ka + 1];
                float dot0 = fmaf(acc_lo[nf][0], INV2048, acc_hh[nf][0]);
                float dot1 = fmaf(acc_lo[nf][1], INV2048, acc_hh[nf][1]);
                float dot2 = fmaf(acc_lo[nf][2], INV2048, acc_hh[nf][2]);
                float dot3 = fmaf(acc_lo[nf][3], INV2048, acc_hh[nf][3]);
                float d0 = (e2a + z2a) - 2.0f * dot0;
                float d1 = (e2b + z2a) - 2.0f * dot1;
                float d2 = (e2a + z2b) - 2.0f * dot2;
                float d3 = (e2b + z2b) - 2.0f * dot3;
                if (d0 < bv0 || (d0 == bv0 && ka     < bk0)) { bv0 = d0; bk0 = ka; }
                if (d1 < bv0 || (d1 == bv0 && ka + 1 < bk0)) { bv0 = d1; bk0 = ka + 1; }
                if (d2 < bv1 || (d2 == bv1 && ka     < bk1)) { bv1 = d2; bk1 = ka; }
                if (d3 < bv1 || (d3 == bv1 && ka + 1 < bk1)) { bv1 = d3; bk1 = ka + 1; }
            }
        }

        if (q + 1 < 64) {
            uint32_t* EhN = smu + OFF_EB + ((buf ^ 1) * 2) * EB_SEG + erow * EST + c2seg;
            uint32_t* ElN = EhN + EB_SEG;
            __half hx = __float2half_rn(pre0.x), hy = __float2half_rn(pre0.y);
            __half hz = __float2half_rn(pre0.z), hw2 = __float2half_rn(pre0.w);
            EhN[0] = h2u(hx, hy); EhN[1] = h2u(hz, hw2);
            ElN[0] = h2u(lo_split(pre0.x, hx), lo_split(pre0.y, hy));
            ElN[1] = h2u(lo_split(pre0.z, hz), lo_split(pre0.w, hw2));
            hx = __float2half_rn(pre1.x); hy = __float2half_rn(pre1.y);
            hz = __float2half_rn(pre1.z); hw2 = __float2half_rn(pre1.w);
            EhN[2] = h2u(hx, hy); EhN[3] = h2u(hz, hw2);
            ElN[2] = h2u(lo_split(pre1.x, hx), lo_split(pre1.y, hy));
            ElN[3] = h2u(lo_split(pre1.z, hz), lo_split(pre1.w, hw2));
        }
        __syncthreads();
    }

    // reduce over the 4 lanes of each group (lexicographic, first-k preference)
#pragma unroll
    for (int off = 1; off <= 2; off <<= 1) {
        float ov0 = __shfl_xor_sync(0xFFFFFFFFu, bv0, off);
        int   ok0 = __shfl_xor_sync(0xFFFFFFFFu, bk0, off);
        float ov1 = __shfl_xor_sync(0xFFFFFFFFu, bv1, off);
        int   ok1 = __shfl_xor_sync(0xFFFFFFFFu, bk1, off);
        if (ov0 < bv0 || (ov0 == bv0 && ok0 < bk0)) { bv0 = ov0; bk0 = ok0; }
        if (ov1 < bv1 || (ov1 == bv1 && ok1 < bk1)) { bv1 = ov1; bk1 = ok1; }
    }

    // cross-warp-row combine via smem (A panel is dead; reuse)
    float* rval = (float*)smu;            // [2][128]
    int*   ridx = (int*)(smu + 256);      // [2][128]
    __syncthreads();
    if (t == 0) {
        rval[wr * 128 + p0] = bv0; ridx[wr * 128 + p0] = bk0;
        rval[wr * 128 + p1] = bv1; ridx[wr * 128 + p1] = bk1;
    }
    __syncthreads();
    if (tid < 128) {
        float v0 = rval[tid];       int k0i = ridx[tid];
        float v1 = rval[128 + tid]; int k1i = ridx[128 + tid];
        int bk;
        if (v1 < v0 || (v1 == v0 && k1i < k0i)) bk = k1i; else bk = k0i;
        int n = n0 + tid;
        g_idx[b * NN + n] = bk;
        long long off = (long long)ZQ_SIZE + b * NN + n;
        if (off < (long long)out_size) dout[off] = (float)bk;
    }
}

// ---------- kernel 5: gather z_q (STE-exact), loss partials ----------
__global__ void k_gather(const float* __restrict__ z, const float* __restrict__ E,
                         float* __restrict__ dout) {
    __shared__ float srow[32 * 257];
    __shared__ int   skid[32];
    __shared__ float sw[8];
    int b = blockIdx.x >> 5, h = blockIdx.x & 31;
    int tid = threadIdx.x;
    int warp = tid >> 5, lane = tid & 31;

    if (tid < 32) skid[tid] = g_idx[b * NN + h * WW + tid];
    __syncthreads();

#pragma unroll
    for (int r2 = 0; r2 < 4; r2++) {
        int r = warp * 4 + r2;
        const float* er = E + skid[r] * CC;
#pragma unroll
        for (int i = 0; i < 8; i++)
            srow[r * 257 + lane + 32 * i] = er[lane + 32 * i];
    }
    __syncthreads();

    int w = lane;
    float local = 0.f;
#pragma unroll 4
    for (int s = 0; s < 32; s++) {
        int c = warp * 32 + s;
        long long zoff = ((long long)(b * CC + c) * HH + h) * WW + w;
        float zv = z[zoff];
        float eq = srow[w * 257 + c];
        float d = eq - zv;
        local = fmaf(d, d, local);
        dout[zoff] = zv + (eq - zv);   // exact straight-through arithmetic
    }
#pragma unroll
    for (int o = 16; o; o >>= 1) local += __shfl_xor_sync(0xFFFFFFFFu, local, o);
    if (lane == 0) sw[warp] = local;
    __syncthreads();
    if (tid == 0) {
        float s2 = 0.f;
#pragma unroll
        for (int i = 0; i < 8; i++) s2 += sw[i];
        g_losspart[blockIdx.x] = s2;
    }
}

// ---------- kernel 6: deterministic loss finalize ----------
__global__ void k_final(float* __restrict__ dout, int out_size) {
    __shared__ float smf[256];
    float s = 0.f;
    for (int i = threadIdx.x; i < 1024; i += 256) s += g_losspart[i];
    smf[threadIdx.x] = s;
    __syncthreads();
    if (threadIdx.x == 0) {
        float t = 0.f;
        for (int i = 0; i < 256; i++) t += smf[i];
        float m = t / 8388608.0f;
        float loss = m + 0.25f * m;
        long long off = (long long)ZQ_SIZE + IDX_SIZE;
        if (off < (long long)out_size) dout[off] = loss;
    }
}

extern "C" void kernel_launch(void* const* d_in, const int* in_sizes, int n_in,
                              void* d_out, int out_size) {
    const float* z = (const float*)d_in[0];
    const float* E = (const float*)d_in[1];
    float* out = (float*)d_out;

    cudaFuncSetAttribute(k_mma, cudaFuncAttributeMaxDynamicSharedMemorySize, SMEM_MMA_BYTES);

    k_e2<<<128, 256>>>(E);
    k_tr<<<1024, 256>>>(z);
    k_z2<<<128, 256>>>();
    k_mma<<<256, 512, SMEM_MMA_BYTES>>>(E, out, out_size);
    if (out_size >= ZQ_SIZE) k_gather<<<1024, 256>>>(z, E, out);
    k_final<<<1, 256>>>(out, out_size);
}